// round 15
// baseline (speedup 1.0000x reference)
#include <cuda_runtime.h>
#include <cuda_bf16.h>
#include <cstdint>

#define N 8192
#define D 128
#define ROWB 256                                   // bytes per row (128 bf16)
#define BM 128
#define BN 128
#define NT_TILES 64
#define NUM_TRI (NT_TILES * (NT_TILES + 1) / 2)   // 2080
#define TILE_BYTES (BM * ROWB)                     // 32768
#define SMEM_BYTES (2 * TILE_BYTES)                // 65536
#define EXP2_2OVLN2 2.885390081777927f             // 2 / ln(2)

// -------- device scratch --------
// g_zn stored PRE-SWIZZLED: byte (row, c) lives at row*256 + (c ^ ((row&7)<<4)).
__device__ __align__(1024) __nv_bfloat16 g_zn[N * D];
__device__ float g_part[2][128][D];   // per-block column-sum partials (no init needed)
__device__ float g_den[N];

__device__ __forceinline__ uint32_t smem_u32(const void* p) {
    uint32_t a;
    asm("{ .reg .u64 t; cvta.to.shared.u64 t, %1; cvt.u32.u64 %0, t; }" : "=r"(a) : "l"(p));
    return a;
}

// -------- kernel 1: normalize rows -> bf16 (swizzled), column-sum partials,
//          zero g_den --------
// grid = 256 x 256thr: 0..127 nodes, 128..255 pair_nodes.
// 8 warps/block; each warp: 8 rows via half-warp ownership (16 lanes/row),
// ALL 8 row-loads (2 float4 each) issued up-front -> MLP=8 per thread.
__global__ void __launch_bounds__(256) prep_kernel(const float* __restrict__ nodes,
                                                   const float* __restrict__ pairn) {
    __shared__ float s_col[8][D];
    const int tid = threadIdx.x;
    const int warp = tid >> 5, lane = tid & 31;
    const int l16 = lane & 15, hw = lane >> 4;
    const bool is_pair = blockIdx.x >= 128;
    const int blk = blockIdx.x & 127;
    const int rb = blk * 64;
    const float* src = is_pair ? pairn : nodes;

    if (!is_pair && tid < 64) g_den[rb + tid] = 0.f;   // safe: simexp runs later

    const int row0 = rb + warp * 8;

    // 8 independent loads up-front (4 slots x 2 float4; half-warp picks row)
    float4 v[4][2];
#pragma unroll
    for (int s = 0; s < 4; s++) {
        const int row = row0 + s * 2 + hw;
        const float4* p = reinterpret_cast<const float4*>(src + (size_t)row * D);
        v[s][0] = p[l16 * 2 + 0];
        v[s][1] = p[l16 * 2 + 1];
    }

    float c[8];
#pragma unroll
    for (int k = 0; k < 8; k++) c[k] = 0.f;

#pragma unroll
    for (int s = 0; s < 4; s++) {
        const int row = row0 + s * 2 + hw;
        float sq = v[s][0].x * v[s][0].x + v[s][0].y * v[s][0].y
                 + v[s][0].z * v[s][0].z + v[s][0].w * v[s][0].w
                 + v[s][1].x * v[s][1].x + v[s][1].y * v[s][1].y
                 + v[s][1].z * v[s][1].z + v[s][1].w * v[s][1].w;
#pragma unroll
        for (int o = 8; o > 0; o >>= 1) sq += __shfl_xor_sync(0xffffffffu, sq, o);
        float scale = rsqrtf(sq);   // norms ~sqrt(128) >> 1e-12 clamp
        float z[8];
        z[0] = v[s][0].x * scale; z[1] = v[s][0].y * scale;
        z[2] = v[s][0].z * scale; z[3] = v[s][0].w * scale;
        z[4] = v[s][1].x * scale; z[5] = v[s][1].y * scale;
        z[6] = v[s][1].z * scale; z[7] = v[s][1].w * scale;
        if (!is_pair) {
            __nv_bfloat162 p0 = __floats2bfloat162_rn(z[0], z[1]);
            __nv_bfloat162 p1 = __floats2bfloat162_rn(z[2], z[3]);
            __nv_bfloat162 p2 = __floats2bfloat162_rn(z[4], z[5]);
            __nv_bfloat162 p3 = __floats2bfloat162_rn(z[6], z[7]);
            uint4 val;
            val.x = *reinterpret_cast<uint32_t*>(&p0);
            val.y = *reinterpret_cast<uint32_t*>(&p1);
            val.z = *reinterpret_cast<uint32_t*>(&p2);
            val.w = *reinterpret_cast<uint32_t*>(&p3);
            uint32_t boff = (uint32_t)(l16 * 16) ^ (uint32_t)((row & 7) << 4);
            *reinterpret_cast<uint4*>(
                reinterpret_cast<char*>(g_zn) + (size_t)row * ROWB + boff) = val;
        }
#pragma unroll
        for (int k = 0; k < 8; k++) c[k] += z[k];
    }
    // fold lane+16 into lane (same columns, different rows)
#pragma unroll
    for (int k = 0; k < 8; k++) c[k] += __shfl_xor_sync(0xffffffffu, c[k], 16);
    if (hw == 0) {
#pragma unroll
        for (int k = 0; k < 8; k++) s_col[warp][l16 * 8 + k] = c[k];
    }
    __syncthreads();
    if (tid < D) {
        float s = 0.f;
#pragma unroll
        for (int w = 0; w < 8; w++) s += s_col[w][tid];
        g_part[is_pair ? 1 : 0][blk][tid] = s;   // plain store, no atomics/init
    }
}

// -------- mma helpers --------
__device__ __forceinline__ void ldmx4(uint32_t r[4], uint32_t addr) {
    asm volatile("ldmatrix.sync.aligned.m8n8.x4.shared.b16 {%0,%1,%2,%3}, [%4];\n"
                 : "=r"(r[0]), "=r"(r[1]), "=r"(r[2]), "=r"(r[3]) : "r"(addr));
}
__device__ __forceinline__ void mma16816(float c[4], const uint32_t a[4],
                                         uint32_t b0, uint32_t b1) {
    asm volatile("mma.sync.aligned.m16n8k16.row.col.f32.bf16.bf16.f32 "
                 "{%0,%1,%2,%3}, {%4,%5,%6,%7}, {%8,%9}, {%0,%1,%2,%3};\n"
                 : "+f"(c[0]), "+f"(c[1]), "+f"(c[2]), "+f"(c[3])
                 : "r"(a[0]), "r"(a[1]), "r"(a[2]), "r"(a[3]), "r"(b0), "r"(b1));
}

// -------- kernel 2: triangular tiles of S = ZN@ZN^T via cp.async.bulk tiles,
//          fused exp row/col sums (symmetry) --------
__global__ void __launch_bounds__(512, 2) simexp_kernel() {
    extern __shared__ char smem[];
    char* sA = smem;
    char* sB = smem + TILE_BYTES;
    __shared__ __align__(8) uint64_t s_mbar;

    const int tid = threadIdx.x;
    const int warp = tid >> 5, lane = tid & 31;

    // triangular decode t -> (ti, tj), tj >= ti
    const int t = blockIdx.x;
    int ti = (int)((129.0f - sqrtf(16641.0f - 8.0f * (float)t)) * 0.5f);
    if (ti > 0 && ti * (2 * NT_TILES + 1 - ti) / 2 > t) ti--;
    while ((ti + 1) * (2 * NT_TILES + 1 - (ti + 1)) / 2 <= t) ti++;
    const int tj = ti + (t - ti * (2 * NT_TILES + 1 - ti) / 2);
    const int i0 = ti * BM;
    const int j0 = tj * BN;
    const bool offdiag = (tj != ti);

    // bulk DMA tile loads (g_zn is pre-swizzled; linear copy preserves layout)
    const uint32_t mb = smem_u32(&s_mbar);
    if (tid == 0) {
        asm volatile("mbarrier.init.shared.b64 [%0], 1;" :: "r"(mb) : "memory");
    }
    __syncthreads();
    if (tid == 0) {
        uint32_t tx = offdiag ? 2 * TILE_BYTES : TILE_BYTES;
        asm volatile("mbarrier.arrive.expect_tx.shared.b64 _, [%0], %1;"
                     :: "r"(mb), "r"(tx) : "memory");
        const char* srcA = reinterpret_cast<const char*>(g_zn) + (size_t)i0 * ROWB;
        asm volatile(
            "cp.async.bulk.shared::cta.global.mbarrier::complete_tx::bytes [%0], [%1], %2, [%3];"
            :: "r"(smem_u32(sA)), "l"(srcA), "r"((uint32_t)TILE_BYTES), "r"(mb) : "memory");
        if (offdiag) {
            const char* srcB = reinterpret_cast<const char*>(g_zn) + (size_t)j0 * ROWB;
            asm volatile(
                "cp.async.bulk.shared::cta.global.mbarrier::complete_tx::bytes [%0], [%1], %2, [%3];"
                :: "r"(smem_u32(sB)), "l"(srcB), "r"((uint32_t)TILE_BYTES), "r"(mb) : "memory");
        }
    }
    {
        uint32_t done;
        asm volatile(
            "{ .reg .pred p; mbarrier.try_wait.parity.acquire.cta.shared::cta.b64 p, [%1], 0;"
            " selp.b32 %0, 1, 0, p; }" : "=r"(done) : "r"(mb) : "memory");
        if (!done) {
            asm volatile(
                "{ .reg .pred P1; WL%=: mbarrier.try_wait.parity.acquire.cta.shared::cta.b64 "
                "P1, [%0], 0, 0x989680; @P1 bra.uni WD%=; bra.uni WL%=; WD%=: }"
                :: "r"(mb) : "memory");
        }
    }

    const uint32_t aBase = smem_u32(sA);
    const uint32_t bBase = offdiag ? smem_u32(sB) : aBase;
    const int wm = (warp & 3) * 32;      // 4 warps along M
    const int wn = (warp >> 2) * 32;     // 4 warps along N

    uint32_t aRow[2], aXor[2];
#pragma unroll
    for (int mt = 0; mt < 2; mt++) {
        int row = wm + mt * 16 + (lane & 15);
        aRow[mt] = aBase + (uint32_t)row * ROWB;
        aXor[mt] = (uint32_t)((row & 7) << 4);
    }
    const uint32_t aCol = (uint32_t)((lane >> 4) * 16);
    const int g = lane >> 3;
    uint32_t bRow[2], bXor[2];
#pragma unroll
    for (int np = 0; np < 2; np++) {
        int row = wn + np * 16 + ((g >> 1) * 8) + (lane & 7);
        bRow[np] = bBase + (uint32_t)row * ROWB;
        bXor[np] = (uint32_t)((row & 7) << 4);
    }
    const uint32_t bCol = (uint32_t)((g & 1) * 16);

    float acc[2][4][4];
#pragma unroll
    for (int mt = 0; mt < 2; mt++)
#pragma unroll
        for (int nt = 0; nt < 4; nt++)
#pragma unroll
            for (int q = 0; q < 4; q++) acc[mt][nt][q] = 0.f;

#pragma unroll
    for (int kt = 0; kt < 8; kt++) {
        const uint32_t kb = (uint32_t)(kt * 32);
        uint32_t afr[2][4];
#pragma unroll
        for (int mt = 0; mt < 2; mt++)
            ldmx4(afr[mt], aRow[mt] + ((kb + aCol) ^ aXor[mt]));
#pragma unroll
        for (int np = 0; np < 2; np++) {
            uint32_t r4[4];
            ldmx4(r4, bRow[np] + ((kb + bCol) ^ bXor[np]));
            mma16816(acc[0][np * 2 + 0], afr[0], r4[0], r4[1]);
            mma16816(acc[0][np * 2 + 1], afr[0], r4[2], r4[3]);
            mma16816(acc[1][np * 2 + 0], afr[1], r4[0], r4[1]);
            mma16816(acc[1][np * 2 + 1], afr[1], r4[2], r4[3]);
        }
    }

    // ---- epilogue: e = exp2(s * 2/ln2) ----
    const int rbase = i0 + wm + (lane >> 2);
    const int cbase = j0 + wn + 2 * (lane & 3);
    const bool has_diag = (!offdiag) && (wm == wn);

    float ccol[4][2];
#pragma unroll
    for (int nt = 0; nt < 4; nt++) { ccol[nt][0] = 0.f; ccol[nt][1] = 0.f; }

#pragma unroll
    for (int mt = 0; mt < 2; mt++) {
#pragma unroll
        for (int half = 0; half < 2; half++) {
            int grow = rbase + mt * 16 + half * 8;
            float p = 0.f;
            if (has_diag) {
#pragma unroll
                for (int nt = 0; nt < 4; nt++) {
                    int gc0 = cbase + nt * 8;
                    float e0 = (grow != gc0)
                             ? exp2f(acc[mt][nt][half * 2 + 0] * EXP2_2OVLN2) : 0.f;
                    float e1 = (grow != gc0 + 1)
                             ? exp2f(acc[mt][nt][half * 2 + 1] * EXP2_2OVLN2) : 0.f;
                    p += e0 + e1;
                }
            } else {
#pragma unroll
                for (int nt = 0; nt < 4; nt++) {
                    float e0 = exp2f(acc[mt][nt][half * 2 + 0] * EXP2_2OVLN2);
                    float e1 = exp2f(acc[mt][nt][half * 2 + 1] * EXP2_2OVLN2);
                    p += e0 + e1;
                    ccol[nt][0] += e0;
                    ccol[nt][1] += e1;
                }
            }
            p += __shfl_xor_sync(0xffffffffu, p, 1);
            p += __shfl_xor_sync(0xffffffffu, p, 2);
            if ((lane & 3) == 0) atomicAdd(&g_den[grow], p);
        }
    }

    if (offdiag) {
#pragma unroll
        for (int nt = 0; nt < 4; nt++) {
#pragma unroll
            for (int c = 0; c < 2; c++) {
                float v = ccol[nt][c];
                v += __shfl_xor_sync(0xffffffffu, v, 4);
                v += __shfl_xor_sync(0xffffffffu, v, 8);
                v += __shfl_xor_sync(0xffffffffu, v, 16);
                if (lane < 4) atomicAdd(&g_den[j0 + wn + nt * 8 + 2 * lane + c], v);
            }
        }
    }
}

// -------- kernel 3: single block; reduce partials + loss (single writer) --------
__global__ void __launch_bounds__(1024) finalize_kernel(float* __restrict__ out) {
    __shared__ float s_red[32];
    __shared__ float s_sz[8][D];
    __shared__ float s_szp[8][D];
    const int tid = threadIdx.x;
    const int warp = tid >> 5, lane = tid & 31;
    const int d = tid & 127, c = tid >> 7;     // 8 chunks x 128 cols

    // reduce column-sum partials: 16 blocks per chunk, coalesced over d
    float a = 0.f, b = 0.f;
#pragma unroll
    for (int k = 0; k < 16; k++) {
        int blk = c * 16 + k;
        a += g_part[0][blk][d];
        b += g_part[1][blk][d];
    }
    s_sz[c][d] = a;
    s_szp[c][d] = b;

    float lg = 0.f;
#pragma unroll
    for (int k = 0; k < N / 1024; k++) lg += __logf(g_den[tid + k * 1024]);
    __syncthreads();
    if (tid < D) {
        float sz = 0.f, szp = 0.f;
#pragma unroll
        for (int q = 0; q < 8; q++) { sz += s_sz[q][tid]; szp += s_szp[q][tid]; }
        lg -= (2.0f / (float)N) * sz * szp;
    }
#pragma unroll
    for (int o = 16; o > 0; o >>= 1) lg += __shfl_xor_sync(0xffffffffu, lg, o);
    if (lane == 0) s_red[warp] = lg;
    __syncthreads();
    if (warp == 0) {
        float v = s_red[lane];
#pragma unroll
        for (int o = 16; o > 0; o >>= 1) v += __shfl_xor_sync(0xffffffffu, v, o);
        if (lane == 0) out[0] = v;
    }
}

extern "C" void kernel_launch(void* const* d_in, const int* in_sizes, int n_in,
                              void* d_out, int out_size) {
    const float* nodes = (const float*)d_in[0];
    const float* pairn = (const float*)d_in[1];
    float* out = (float*)d_out;

    cudaFuncSetAttribute(simexp_kernel, cudaFuncAttributeMaxDynamicSharedMemorySize, SMEM_BYTES);

    prep_kernel<<<256, 256>>>(nodes, pairn);
    simexp_kernel<<<NUM_TRI, 512, SMEM_BYTES>>>();
    finalize_kernel<<<1, 1024>>>(out);
}

// round 16
// speedup vs baseline: 1.4565x; 1.4565x over previous
#include <cuda_runtime.h>
#include <cuda_bf16.h>
#include <cstdint>

#define N 8192
#define D 128
#define ROWB 256                                   // bytes per row (128 bf16)
#define BM 128
#define BN 128
#define NT_TILES 64
#define NUM_TRI (NT_TILES * (NT_TILES + 1) / 2)   // 2080
#define TILE_BYTES (BM * ROWB)                     // 32768
#define SMEM_BYTES (2 * TILE_BYTES)                // 65536
#define EXP2_2OVLN2 2.885390081777927f             // 2 / ln(2)

// -------- device scratch --------
// g_zn stored PRE-SWIZZLED: byte (row, c) lives at row*256 + (c ^ ((row&7)<<4)).
__device__ __align__(1024) __nv_bfloat16 g_zn[N * D];
struct Scratch { float sumz[D]; float sumzp[D]; };
__device__ Scratch g_s;
__device__ float g_den[N];

__device__ __forceinline__ uint32_t smem_u32(const void* p) {
    uint32_t a;
    asm("{ .reg .u64 t; cvta.to.shared.u64 t, %1; cvt.u32.u64 %0, t; }" : "=r"(a) : "l"(p));
    return a;
}

// -------- kernel 1: normalize rows -> bf16 (swizzled), column sums, zero g_den ----
// grid = 256 x 256thr: 0..127 nodes, 128..255 pair_nodes.
// 8 warps/block; each warp: 8 rows via half-warp ownership (16 lanes/row),
// ALL 8 row-loads (2 float4 each) issued up-front -> MLP=8 per thread.
__global__ void __launch_bounds__(256) prep_kernel(const float* __restrict__ nodes,
                                                   const float* __restrict__ pairn) {
    __shared__ float s_col[8][D];
    const int tid = threadIdx.x;
    const int warp = tid >> 5, lane = tid & 31;
    const int l16 = lane & 15, hw = lane >> 4;
    const bool is_pair = blockIdx.x >= 128;
    const int rb = (blockIdx.x & 127) * 64;
    const float* src = is_pair ? pairn : nodes;

    if (!is_pair && tid < 64) g_den[rb + tid] = 0.f;   // safe: simexp runs later

    const int row0 = rb + warp * 8;

    // 8 independent loads up-front (4 slots x 2 float4; half-warp picks row)
    float4 v[4][2];
#pragma unroll
    for (int s = 0; s < 4; s++) {
        const int row = row0 + s * 2 + hw;
        const float4* p = reinterpret_cast<const float4*>(src + (size_t)row * D);
        v[s][0] = p[l16 * 2 + 0];
        v[s][1] = p[l16 * 2 + 1];
    }

    float c[8];
#pragma unroll
    for (int k = 0; k < 8; k++) c[k] = 0.f;

#pragma unroll
    for (int s = 0; s < 4; s++) {
        const int row = row0 + s * 2 + hw;
        float sq = v[s][0].x * v[s][0].x + v[s][0].y * v[s][0].y
                 + v[s][0].z * v[s][0].z + v[s][0].w * v[s][0].w
                 + v[s][1].x * v[s][1].x + v[s][1].y * v[s][1].y
                 + v[s][1].z * v[s][1].z + v[s][1].w * v[s][1].w;
#pragma unroll
        for (int o = 8; o > 0; o >>= 1) sq += __shfl_xor_sync(0xffffffffu, sq, o);
        float scale = rsqrtf(sq);   // norms ~sqrt(128) >> 1e-12 clamp
        float z[8];
        z[0] = v[s][0].x * scale; z[1] = v[s][0].y * scale;
        z[2] = v[s][0].z * scale; z[3] = v[s][0].w * scale;
        z[4] = v[s][1].x * scale; z[5] = v[s][1].y * scale;
        z[6] = v[s][1].z * scale; z[7] = v[s][1].w * scale;
        if (!is_pair) {
            __nv_bfloat162 p0 = __floats2bfloat162_rn(z[0], z[1]);
            __nv_bfloat162 p1 = __floats2bfloat162_rn(z[2], z[3]);
            __nv_bfloat162 p2 = __floats2bfloat162_rn(z[4], z[5]);
            __nv_bfloat162 p3 = __floats2bfloat162_rn(z[6], z[7]);
            uint4 val;
            val.x = *reinterpret_cast<uint32_t*>(&p0);
            val.y = *reinterpret_cast<uint32_t*>(&p1);
            val.z = *reinterpret_cast<uint32_t*>(&p2);
            val.w = *reinterpret_cast<uint32_t*>(&p3);
            uint32_t boff = (uint32_t)(l16 * 16) ^ (uint32_t)((row & 7) << 4);
            *reinterpret_cast<uint4*>(
                reinterpret_cast<char*>(g_zn) + (size_t)row * ROWB + boff) = val;
        }
#pragma unroll
        for (int k = 0; k < 8; k++) c[k] += z[k];
    }
    // fold lane+16 into lane (same columns, different rows)
#pragma unroll
    for (int k = 0; k < 8; k++) c[k] += __shfl_xor_sync(0xffffffffu, c[k], 16);
    if (hw == 0) {
#pragma unroll
        for (int k = 0; k < 8; k++) s_col[warp][l16 * 8 + k] = c[k];
    }
    __syncthreads();
    if (tid < D) {
        float s = 0.f;
#pragma unroll
        for (int w = 0; w < 8; w++) s += s_col[w][tid];
        atomicAdd(is_pair ? &g_s.sumzp[tid] : &g_s.sumz[tid], s);
    }
}

// -------- mma helpers --------
__device__ __forceinline__ void ldmx4(uint32_t r[4], uint32_t addr) {
    asm volatile("ldmatrix.sync.aligned.m8n8.x4.shared.b16 {%0,%1,%2,%3}, [%4];\n"
                 : "=r"(r[0]), "=r"(r[1]), "=r"(r[2]), "=r"(r[3]) : "r"(addr));
}
__device__ __forceinline__ void mma16816(float c[4], const uint32_t a[4],
                                         uint32_t b0, uint32_t b1) {
    asm volatile("mma.sync.aligned.m16n8k16.row.col.f32.bf16.bf16.f32 "
                 "{%0,%1,%2,%3}, {%4,%5,%6,%7}, {%8,%9}, {%0,%1,%2,%3};\n"
                 : "+f"(c[0]), "+f"(c[1]), "+f"(c[2]), "+f"(c[3])
                 : "r"(a[0]), "r"(a[1]), "r"(a[2]), "r"(a[3]), "r"(b0), "r"(b1));
}

// -------- kernel 2: triangular tiles of S = ZN@ZN^T via cp.async.bulk tiles,
//          fused exp row/col sums (symmetry) --------
__global__ void __launch_bounds__(512, 2) simexp_kernel() {
    extern __shared__ char smem[];
    char* sA = smem;
    char* sB = smem + TILE_BYTES;
    __shared__ __align__(8) uint64_t s_mbar;

    const int tid = threadIdx.x;
    const int warp = tid >> 5, lane = tid & 31;

    // triangular decode t -> (ti, tj), tj >= ti
    const int t = blockIdx.x;
    int ti = (int)((129.0f - sqrtf(16641.0f - 8.0f * (float)t)) * 0.5f);
    if (ti > 0 && ti * (2 * NT_TILES + 1 - ti) / 2 > t) ti--;
    while ((ti + 1) * (2 * NT_TILES + 1 - (ti + 1)) / 2 <= t) ti++;
    const int tj = ti + (t - ti * (2 * NT_TILES + 1 - ti) / 2);
    const int i0 = ti * BM;
    const int j0 = tj * BN;
    const bool offdiag = (tj != ti);

    // bulk DMA tile loads (g_zn is pre-swizzled; linear copy preserves layout)
    const uint32_t mb = smem_u32(&s_mbar);
    if (tid == 0) {
        asm volatile("mbarrier.init.shared.b64 [%0], 1;" :: "r"(mb) : "memory");
    }
    __syncthreads();
    if (tid == 0) {
        uint32_t tx = offdiag ? 2 * TILE_BYTES : TILE_BYTES;
        asm volatile("mbarrier.arrive.expect_tx.shared.b64 _, [%0], %1;"
                     :: "r"(mb), "r"(tx) : "memory");
        const char* srcA = reinterpret_cast<const char*>(g_zn) + (size_t)i0 * ROWB;
        asm volatile(
            "cp.async.bulk.shared::cta.global.mbarrier::complete_tx::bytes [%0], [%1], %2, [%3];"
            :: "r"(smem_u32(sA)), "l"(srcA), "r"((uint32_t)TILE_BYTES), "r"(mb) : "memory");
        if (offdiag) {
            const char* srcB = reinterpret_cast<const char*>(g_zn) + (size_t)j0 * ROWB;
            asm volatile(
                "cp.async.bulk.shared::cta.global.mbarrier::complete_tx::bytes [%0], [%1], %2, [%3];"
                :: "r"(smem_u32(sB)), "l"(srcB), "r"((uint32_t)TILE_BYTES), "r"(mb) : "memory");
        }
    }
    {
        uint32_t done;
        asm volatile(
            "{ .reg .pred p; mbarrier.try_wait.parity.acquire.cta.shared::cta.b64 p, [%1], 0;"
            " selp.b32 %0, 1, 0, p; }" : "=r"(done) : "r"(mb) : "memory");
        if (!done) {
            asm volatile(
                "{ .reg .pred P1; WL%=: mbarrier.try_wait.parity.acquire.cta.shared::cta.b64 "
                "P1, [%0], 0, 0x989680; @P1 bra.uni WD%=; bra.uni WL%=; WD%=: }"
                :: "r"(mb) : "memory");
        }
    }

    const uint32_t aBase = smem_u32(sA);
    const uint32_t bBase = offdiag ? smem_u32(sB) : aBase;
    const int wm = (warp & 3) * 32;      // 4 warps along M
    const int wn = (warp >> 2) * 32;     // 4 warps along N

    uint32_t aRow[2], aXor[2];
#pragma unroll
    for (int mt = 0; mt < 2; mt++) {
        int row = wm + mt * 16 + (lane & 15);
        aRow[mt] = aBase + (uint32_t)row * ROWB;
        aXor[mt] = (uint32_t)((row & 7) << 4);
    }
    const uint32_t aCol = (uint32_t)((lane >> 4) * 16);
    const int g = lane >> 3;
    uint32_t bRow[2], bXor[2];
#pragma unroll
    for (int np = 0; np < 2; np++) {
        int row = wn + np * 16 + ((g >> 1) * 8) + (lane & 7);
        bRow[np] = bBase + (uint32_t)row * ROWB;
        bXor[np] = (uint32_t)((row & 7) << 4);
    }
    const uint32_t bCol = (uint32_t)((g & 1) * 16);

    float acc[2][4][4];
#pragma unroll
    for (int mt = 0; mt < 2; mt++)
#pragma unroll
        for (int nt = 0; nt < 4; nt++)
#pragma unroll
            for (int q = 0; q < 4; q++) acc[mt][nt][q] = 0.f;

#pragma unroll
    for (int kt = 0; kt < 8; kt++) {
        const uint32_t kb = (uint32_t)(kt * 32);
        uint32_t afr[2][4];
#pragma unroll
        for (int mt = 0; mt < 2; mt++)
            ldmx4(afr[mt], aRow[mt] + ((kb + aCol) ^ aXor[mt]));
#pragma unroll
        for (int np = 0; np < 2; np++) {
            uint32_t r4[4];
            ldmx4(r4, bRow[np] + ((kb + bCol) ^ bXor[np]));
            mma16816(acc[0][np * 2 + 0], afr[0], r4[0], r4[1]);
            mma16816(acc[0][np * 2 + 1], afr[0], r4[2], r4[3]);
            mma16816(acc[1][np * 2 + 0], afr[1], r4[0], r4[1]);
            mma16816(acc[1][np * 2 + 1], afr[1], r4[2], r4[3]);
        }
    }

    // ---- epilogue: e = exp2(s * 2/ln2) ----
    const int rbase = i0 + wm + (lane >> 2);
    const int cbase = j0 + wn + 2 * (lane & 3);
    const bool has_diag = (!offdiag) && (wm == wn);

    float ccol[4][2];
#pragma unroll
    for (int nt = 0; nt < 4; nt++) { ccol[nt][0] = 0.f; ccol[nt][1] = 0.f; }

#pragma unroll
    for (int mt = 0; mt < 2; mt++) {
#pragma unroll
        for (int half = 0; half < 2; half++) {
            int grow = rbase + mt * 16 + half * 8;
            float p = 0.f;
            if (has_diag) {
#pragma unroll
                for (int nt = 0; nt < 4; nt++) {
                    int gc0 = cbase + nt * 8;
                    float e0 = (grow != gc0)
                             ? exp2f(acc[mt][nt][half * 2 + 0] * EXP2_2OVLN2) : 0.f;
                    float e1 = (grow != gc0 + 1)
                             ? exp2f(acc[mt][nt][half * 2 + 1] * EXP2_2OVLN2) : 0.f;
                    p += e0 + e1;
                }
            } else {
#pragma unroll
                for (int nt = 0; nt < 4; nt++) {
                    float e0 = exp2f(acc[mt][nt][half * 2 + 0] * EXP2_2OVLN2);
                    float e1 = exp2f(acc[mt][nt][half * 2 + 1] * EXP2_2OVLN2);
                    p += e0 + e1;
                    ccol[nt][0] += e0;
                    ccol[nt][1] += e1;
                }
            }
            p += __shfl_xor_sync(0xffffffffu, p, 1);
            p += __shfl_xor_sync(0xffffffffu, p, 2);
            if ((lane & 3) == 0) atomicAdd(&g_den[grow], p);
        }
    }

    if (offdiag) {
#pragma unroll
        for (int nt = 0; nt < 4; nt++) {
#pragma unroll
            for (int c = 0; c < 2; c++) {
                float v = ccol[nt][c];
                v += __shfl_xor_sync(0xffffffffu, v, 4);
                v += __shfl_xor_sync(0xffffffffu, v, 8);
                v += __shfl_xor_sync(0xffffffffu, v, 16);
                if (lane < 4) atomicAdd(&g_den[j0 + wn + nt * 8 + 2 * lane + c], v);
            }
        }
    }
}

// -------- kernel 3: single block, single-writer loss --------
__global__ void __launch_bounds__(1024) finalize_kernel(float* __restrict__ out) {
    __shared__ float s_red[32];
    const int tid = threadIdx.x;
    const int warp = tid >> 5, lane = tid & 31;
    float lg = 0.f;
#pragma unroll
    for (int k = 0; k < N / 1024; k++) lg += __logf(g_den[tid + k * 1024]);
    if (tid < D) lg -= (2.0f / (float)N) * g_s.sumz[tid] * g_s.sumzp[tid];
#pragma unroll
    for (int o = 16; o > 0; o >>= 1) lg += __shfl_xor_sync(0xffffffffu, lg, o);
    if (lane == 0) s_red[warp] = lg;
    __syncthreads();
    if (warp == 0) {
        float v = s_red[lane];
#pragma unroll
        for (int o = 16; o > 0; o >>= 1) v += __shfl_xor_sync(0xffffffffu, v, o);
        if (lane == 0) out[0] = v;
    }
}

extern "C" void kernel_launch(void* const* d_in, const int* in_sizes, int n_in,
                              void* d_out, int out_size) {
    const float* nodes = (const float*)d_in[0];
    const float* pairn = (const float*)d_in[1];
    float* out = (float*)d_out;

    void* scratch_ptr = nullptr;
    cudaGetSymbolAddress(&scratch_ptr, g_s);
    cudaFuncSetAttribute(simexp_kernel, cudaFuncAttributeMaxDynamicSharedMemorySize, SMEM_BYTES);

    cudaMemsetAsync(scratch_ptr, 0, sizeof(Scratch));
    prep_kernel<<<256, 256>>>(nodes, pairn);
    simexp_kernel<<<NUM_TRI, 512, SMEM_BYTES>>>();
    finalize_kernel<<<1, 1024>>>(out);
}

// round 17
// speedup vs baseline: 1.5331x; 1.0526x over previous
#include <cuda_runtime.h>
#include <cuda_bf16.h>
#include <cstdint>

#define N 8192
#define D 128
#define ROWB 256                                   // bytes per row (128 bf16)
#define BM 128
#define BN 128
#define NT_TILES 64
#define NUM_TRI (NT_TILES * (NT_TILES + 1) / 2)   // 2080
#define TILE_BYTES (BM * ROWB)                     // 32768
#define SMEM_BYTES (2 * TILE_BYTES)                // 65536
#define ALPHA 1.69864362f                          // sqrt(2/ln2); ALPHA^2 = 2.8853901

// -------- device scratch --------
// g_zn stored PRE-SWIZZLED and PRE-SCALED by ALPHA:
// byte (row, c) lives at row*256 + (c ^ ((row&7)<<4));  S = (2/ln2)*cos -> exp2(S).
__device__ __align__(1024) __nv_bfloat16 g_zn[N * D];
struct Scratch { float sumz[D]; float sumzp[D]; };
__device__ Scratch g_s;
__device__ float g_den[N];

__device__ __forceinline__ uint32_t smem_u32(const void* p) {
    uint32_t a;
    asm("{ .reg .u64 t; cvta.to.shared.u64 t, %1; cvt.u32.u64 %0, t; }" : "=r"(a) : "l"(p));
    return a;
}
__device__ __forceinline__ float ex2(float x) {
    float y;
    asm("ex2.approx.ftz.f32 %0, %1;" : "=f"(y) : "f"(x));
    return y;
}

// -------- kernel 1: normalize rows -> bf16*ALPHA (swizzled), column sums,
//          zero g_den --------
// grid = 256 x 256thr: 0..127 nodes, 128..255 pair_nodes.
// 8 warps/block; each warp: 8 rows via half-warp ownership (16 lanes/row),
// ALL 8 row-loads (2 float4 each) issued up-front -> MLP=8 per thread.
__global__ void __launch_bounds__(256) prep_kernel(const float* __restrict__ nodes,
                                                   const float* __restrict__ pairn) {
    __shared__ float s_col[8][D];
    const int tid = threadIdx.x;
    const int warp = tid >> 5, lane = tid & 31;
    const int l16 = lane & 15, hw = lane >> 4;
    const bool is_pair = blockIdx.x >= 128;
    const int rb = (blockIdx.x & 127) * 64;
    const float* src = is_pair ? pairn : nodes;

    if (!is_pair && tid < 64) g_den[rb + tid] = 0.f;   // safe: simexp runs later

    const int row0 = rb + warp * 8;

    // 8 independent loads up-front (4 slots x 2 float4; half-warp picks row)
    float4 v[4][2];
#pragma unroll
    for (int s = 0; s < 4; s++) {
        const int row = row0 + s * 2 + hw;
        const float4* p = reinterpret_cast<const float4*>(src + (size_t)row * D);
        v[s][0] = p[l16 * 2 + 0];
        v[s][1] = p[l16 * 2 + 1];
    }

    float c[8];
#pragma unroll
    for (int k = 0; k < 8; k++) c[k] = 0.f;

#pragma unroll
    for (int s = 0; s < 4; s++) {
        const int row = row0 + s * 2 + hw;
        float sq = v[s][0].x * v[s][0].x + v[s][0].y * v[s][0].y
                 + v[s][0].z * v[s][0].z + v[s][0].w * v[s][0].w
                 + v[s][1].x * v[s][1].x + v[s][1].y * v[s][1].y
                 + v[s][1].z * v[s][1].z + v[s][1].w * v[s][1].w;
#pragma unroll
        for (int o = 8; o > 0; o >>= 1) sq += __shfl_xor_sync(0xffffffffu, sq, o);
        float scale = rsqrtf(sq);   // norms ~sqrt(128) >> 1e-12 clamp
        float z[8];
        z[0] = v[s][0].x * scale; z[1] = v[s][0].y * scale;
        z[2] = v[s][0].z * scale; z[3] = v[s][0].w * scale;
        z[4] = v[s][1].x * scale; z[5] = v[s][1].y * scale;
        z[6] = v[s][1].z * scale; z[7] = v[s][1].w * scale;
        if (!is_pair) {
            // store w = ALPHA * z so S = w.w^T = (2/ln2) cos -> epilogue exp2(S)
            __nv_bfloat162 p0 = __floats2bfloat162_rn(z[0] * ALPHA, z[1] * ALPHA);
            __nv_bfloat162 p1 = __floats2bfloat162_rn(z[2] * ALPHA, z[3] * ALPHA);
            __nv_bfloat162 p2 = __floats2bfloat162_rn(z[4] * ALPHA, z[5] * ALPHA);
            __nv_bfloat162 p3 = __floats2bfloat162_rn(z[6] * ALPHA, z[7] * ALPHA);
            uint4 val;
            val.x = *reinterpret_cast<uint32_t*>(&p0);
            val.y = *reinterpret_cast<uint32_t*>(&p1);
            val.z = *reinterpret_cast<uint32_t*>(&p2);
            val.w = *reinterpret_cast<uint32_t*>(&p3);
            uint32_t boff = (uint32_t)(l16 * 16) ^ (uint32_t)((row & 7) << 4);
            *reinterpret_cast<uint4*>(
                reinterpret_cast<char*>(g_zn) + (size_t)row * ROWB + boff) = val;
        }
#pragma unroll
        for (int k = 0; k < 8; k++) c[k] += z[k];   // UNscaled sums for nominator
    }
    // fold lane+16 into lane (same columns, different rows)
#pragma unroll
    for (int k = 0; k < 8; k++) c[k] += __shfl_xor_sync(0xffffffffu, c[k], 16);
    if (hw == 0) {
#pragma unroll
        for (int k = 0; k < 8; k++) s_col[warp][l16 * 8 + k] = c[k];
    }
    __syncthreads();
    if (tid < D) {
        float s = 0.f;
#pragma unroll
        for (int w = 0; w < 8; w++) s += s_col[w][tid];
        atomicAdd(is_pair ? &g_s.sumzp[tid] : &g_s.sumz[tid], s);
    }
}

// -------- mma helpers --------
__device__ __forceinline__ void ldmx4(uint32_t r[4], uint32_t addr) {
    asm volatile("ldmatrix.sync.aligned.m8n8.x4.shared.b16 {%0,%1,%2,%3}, [%4];\n"
                 : "=r"(r[0]), "=r"(r[1]), "=r"(r[2]), "=r"(r[3]) : "r"(addr));
}
__device__ __forceinline__ void mma16816(float c[4], const uint32_t a[4],
                                         uint32_t b0, uint32_t b1) {
    asm volatile("mma.sync.aligned.m16n8k16.row.col.f32.bf16.bf16.f32 "
                 "{%0,%1,%2,%3}, {%4,%5,%6,%7}, {%8,%9}, {%0,%1,%2,%3};\n"
                 : "+f"(c[0]), "+f"(c[1]), "+f"(c[2]), "+f"(c[3])
                 : "r"(a[0]), "r"(a[1]), "r"(a[2]), "r"(a[3]), "r"(b0), "r"(b1));
}

// -------- kernel 2: triangular tiles of S = W@W^T via cp.async.bulk tiles,
//          fused exp2 row/col sums (symmetry) --------
__global__ void __launch_bounds__(512, 2) simexp_kernel() {
    extern __shared__ char smem[];
    char* sA = smem;
    char* sB = smem + TILE_BYTES;
    __shared__ __align__(8) uint64_t s_mbar;

    const int tid = threadIdx.x;
    const int warp = tid >> 5, lane = tid & 31;

    // triangular decode t -> (ti, tj), tj >= ti
    const int t = blockIdx.x;
    int ti = (int)((129.0f - sqrtf(16641.0f - 8.0f * (float)t)) * 0.5f);
    if (ti > 0 && ti * (2 * NT_TILES + 1 - ti) / 2 > t) ti--;
    while ((ti + 1) * (2 * NT_TILES + 1 - (ti + 1)) / 2 <= t) ti++;
    const int tj = ti + (t - ti * (2 * NT_TILES + 1 - ti) / 2);
    const int i0 = ti * BM;
    const int j0 = tj * BN;
    const bool offdiag = (tj != ti);

    // bulk DMA tile loads (g_zn is pre-swizzled; linear copy preserves layout)
    const uint32_t mb = smem_u32(&s_mbar);
    if (tid == 0) {
        asm volatile("mbarrier.init.shared.b64 [%0], 1;" :: "r"(mb) : "memory");
    }
    __syncthreads();
    if (tid == 0) {
        uint32_t tx = offdiag ? 2 * TILE_BYTES : TILE_BYTES;
        asm volatile("mbarrier.arrive.expect_tx.shared.b64 _, [%0], %1;"
                     :: "r"(mb), "r"(tx) : "memory");
        const char* srcA = reinterpret_cast<const char*>(g_zn) + (size_t)i0 * ROWB;
        asm volatile(
            "cp.async.bulk.shared::cta.global.mbarrier::complete_tx::bytes [%0], [%1], %2, [%3];"
            :: "r"(smem_u32(sA)), "l"(srcA), "r"((uint32_t)TILE_BYTES), "r"(mb) : "memory");
        if (offdiag) {
            const char* srcB = reinterpret_cast<const char*>(g_zn) + (size_t)j0 * ROWB;
            asm volatile(
                "cp.async.bulk.shared::cta.global.mbarrier::complete_tx::bytes [%0], [%1], %2, [%3];"
                :: "r"(smem_u32(sB)), "l"(srcB), "r"((uint32_t)TILE_BYTES), "r"(mb) : "memory");
        }
    }
    {
        uint32_t done;
        asm volatile(
            "{ .reg .pred p; mbarrier.try_wait.parity.acquire.cta.shared::cta.b64 p, [%1], 0;"
            " selp.b32 %0, 1, 0, p; }" : "=r"(done) : "r"(mb) : "memory");
        if (!done) {
            asm volatile(
                "{ .reg .pred P1; WL%=: mbarrier.try_wait.parity.acquire.cta.shared::cta.b64 "
                "P1, [%0], 0, 0x989680; @P1 bra.uni WD%=; bra.uni WL%=; WD%=: }"
                :: "r"(mb) : "memory");
        }
    }

    const uint32_t aBase = smem_u32(sA);
    const uint32_t bBase = offdiag ? smem_u32(sB) : aBase;
    const int wm = (warp & 3) * 32;      // 4 warps along M
    const int wn = (warp >> 2) * 32;     // 4 warps along N

    uint32_t aRow[2], aXor[2];
#pragma unroll
    for (int mt = 0; mt < 2; mt++) {
        int row = wm + mt * 16 + (lane & 15);
        aRow[mt] = aBase + (uint32_t)row * ROWB;
        aXor[mt] = (uint32_t)((row & 7) << 4);
    }
    const uint32_t aCol = (uint32_t)((lane >> 4) * 16);
    const int g = lane >> 3;
    uint32_t bRow[2], bXor[2];
#pragma unroll
    for (int np = 0; np < 2; np++) {
        int row = wn + np * 16 + ((g >> 1) * 8) + (lane & 7);
        bRow[np] = bBase + (uint32_t)row * ROWB;
        bXor[np] = (uint32_t)((row & 7) << 4);
    }
    const uint32_t bCol = (uint32_t)((g & 1) * 16);

    float acc[2][4][4];
#pragma unroll
    for (int mt = 0; mt < 2; mt++)
#pragma unroll
        for (int nt = 0; nt < 4; nt++)
#pragma unroll
            for (int q = 0; q < 4; q++) acc[mt][nt][q] = 0.f;

#pragma unroll
    for (int kt = 0; kt < 8; kt++) {
        const uint32_t kb = (uint32_t)(kt * 32);
        uint32_t afr[2][4];
#pragma unroll
        for (int mt = 0; mt < 2; mt++)
            ldmx4(afr[mt], aRow[mt] + ((kb + aCol) ^ aXor[mt]));
#pragma unroll
        for (int np = 0; np < 2; np++) {
            uint32_t r4[4];
            ldmx4(r4, bRow[np] + ((kb + bCol) ^ bXor[np]));
            mma16816(acc[0][np * 2 + 0], afr[0], r4[0], r4[1]);
            mma16816(acc[0][np * 2 + 1], afr[0], r4[2], r4[3]);
            mma16816(acc[1][np * 2 + 0], afr[1], r4[0], r4[1]);
            mma16816(acc[1][np * 2 + 1], afr[1], r4[2], r4[3]);
        }
    }

    // ---- epilogue: e = exp2(s)  (temperature pre-folded into data) ----
    const int rbase = i0 + wm + (lane >> 2);
    const int cbase = j0 + wn + 2 * (lane & 3);
    const bool has_diag = (!offdiag) && (wm == wn);

    float ccol[4][2];
#pragma unroll
    for (int nt = 0; nt < 4; nt++) { ccol[nt][0] = 0.f; ccol[nt][1] = 0.f; }

#pragma unroll
    for (int mt = 0; mt < 2; mt++) {
#pragma unroll
        for (int half = 0; half < 2; half++) {
            int grow = rbase + mt * 16 + half * 8;
            float p = 0.f;
            if (has_diag) {
#pragma unroll
                for (int nt = 0; nt < 4; nt++) {
                    int gc0 = cbase + nt * 8;
                    float e0 = (grow != gc0)
                             ? ex2(acc[mt][nt][half * 2 + 0]) : 0.f;
                    float e1 = (grow != gc0 + 1)
                             ? ex2(acc[mt][nt][half * 2 + 1]) : 0.f;
                    p += e0 + e1;
                }
            } else {
#pragma unroll
                for (int nt = 0; nt < 4; nt++) {
                    float e0 = ex2(acc[mt][nt][half * 2 + 0]);
                    float e1 = ex2(acc[mt][nt][half * 2 + 1]);
                    p += e0 + e1;
                    ccol[nt][0] += e0;
                    ccol[nt][1] += e1;
                }
            }
            p += __shfl_xor_sync(0xffffffffu, p, 1);
            p += __shfl_xor_sync(0xffffffffu, p, 2);
            if ((lane & 3) == 0) atomicAdd(&g_den[grow], p);
        }
    }

    if (offdiag) {
#pragma unroll
        for (int nt = 0; nt < 4; nt++) {
#pragma unroll
            for (int c = 0; c < 2; c++) {
                float v = ccol[nt][c];
                v += __shfl_xor_sync(0xffffffffu, v, 4);
                v += __shfl_xor_sync(0xffffffffu, v, 8);
                v += __shfl_xor_sync(0xffffffffu, v, 16);
                if (lane < 4) atomicAdd(&g_den[j0 + wn + nt * 8 + 2 * lane + c], v);
            }
        }
    }
}

// -------- kernel 3: single block, single-writer loss --------
__global__ void __launch_bounds__(1024) finalize_kernel(float* __restrict__ out) {
    __shared__ float s_red[32];
    const int tid = threadIdx.x;
    const int warp = tid >> 5, lane = tid & 31;
    float lg = 0.f;
#pragma unroll
    for (int k = 0; k < N / 1024; k++) lg += __logf(g_den[tid + k * 1024]);
    if (tid < D) lg -= (2.0f / (float)N) * g_s.sumz[tid] * g_s.sumzp[tid];
#pragma unroll
    for (int o = 16; o > 0; o >>= 1) lg += __shfl_xor_sync(0xffffffffu, lg, o);
    if (lane == 0) s_red[warp] = lg;
    __syncthreads();
    if (warp == 0) {
        float v = s_red[lane];
#pragma unroll
        for (int o = 16; o > 0; o >>= 1) v += __shfl_xor_sync(0xffffffffu, v, o);
        if (lane == 0) out[0] = v;
    }
}

extern "C" void kernel_launch(void* const* d_in, const int* in_sizes, int n_in,
                              void* d_out, int out_size) {
    const float* nodes = (const float*)d_in[0];
    const float* pairn = (const float*)d_in[1];
    float* out = (float*)d_out;

    void* scratch_ptr = nullptr;
    cudaGetSymbolAddress(&scratch_ptr, g_s);
    cudaFuncSetAttribute(simexp_kernel, cudaFuncAttributeMaxDynamicSharedMemorySize, SMEM_BYTES);

    cudaMemsetAsync(scratch_ptr, 0, sizeof(Scratch));
    prep_kernel<<<256, 256>>>(nodes, pairn);
    simexp_kernel<<<NUM_TRI, 512, SMEM_BYTES>>>();
    finalize_kernel<<<1, 1024>>>(out);
}